// round 4
// baseline (speedup 1.0000x reference)
#include <cuda_runtime.h>
#include <math.h>

// YOLO loss reduction, fully fused single launch.
// n cells (802816): pred 30 f32, tbox 4 f32, tcls 20 f32, mask 1 elem (dtype
// detected inline). Outputs 5 f32: total, reg, containing, noobj, cls.

#define S_GRID_INV (1.0f / 14.0f)
#define L_COORD 5.0f
#define L_NOOBJ 0.5f
#define TPB 256

__device__ double g_acc[4];        // cls, noobj(raw), reg(raw), containing
__device__ unsigned g_counter;     // zero-initialized; reset to 0 by last block

__global__ void __launch_bounds__(TPB) yolo_fused_kernel(
    const float* __restrict__ pred,
    const float* __restrict__ tbox,
    const float* __restrict__ tcls,
    const void* __restrict__ maskv,
    int ncell, int n_batch, float* __restrict__ out)
{
    __shared__ float sp[TPB * 30];   // pred tile  (30 KB)
    __shared__ float st[TPB * 20];   // tcls tile  (20 KB)
    __shared__ int s_gt1, s_bad;
    __shared__ bool s_last;

    const int tid = threadIdx.x;
    const int block0 = blockIdx.x * TPB;

    if (tid == 0) { s_gt1 = 0; s_bad = 0; }
    __syncthreads();

    // ---- inline mask dtype detection (first 256 words; deterministic) ----
    {
        unsigned w = ((const unsigned*)maskv)[tid];
        bool gt1 = w > 1u;
        bool bad = ((w & 0xFFu) > 1u) | (((w >> 8) & 0xFFu) > 1u) |
                   (((w >> 16) & 0xFFu) > 1u) | ((w >> 24) > 1u);
        unsigned bg = __ballot_sync(0xFFFFFFFFu, gt1);
        unsigned bb = __ballot_sync(0xFFFFFFFFu, bad);
        if ((tid & 31) == 0) {
            if (bg) atomicOr(&s_gt1, 1);
            if (bb) atomicOr(&s_bad, 1);
        }
    }

    // ---- coalesced staging into smem (streaming loads, read-once data) ----
    {
        const float2* gp2 = (const float2*)(pred + (size_t)block0 * 30);
        float2* sp2 = (float2*)sp;
        long long lim_p = ((long long)ncell - block0) * 30 / 2;
#pragma unroll
        for (int k = 0; k < 15; k++) {
            int i = tid + k * TPB;
            if (i < lim_p) sp2[i] = __ldcs(gp2 + i);
        }
        const float4* gt4 = (const float4*)(tcls + (size_t)block0 * 20);
        float4* st4 = (float4*)st;
        long long lim_t = ((long long)ncell - block0) * 20 / 4;
#pragma unroll
        for (int k = 0; k < 5; k++) {
            int i = tid + k * TPB;
            if (i < lim_t) st4[i] = __ldcs(gt4 + i);
        }
    }
    __syncthreads();

    const int mode = (s_gt1 == 0) ? 0 : (s_bad ? 2 : 1);

    float s_cls = 0.f, s_noobj = 0.f, s_reg = 0.f, s_cont = 0.f;

    const int c = block0 + tid;
    if (c < ncell) {
        bool m;
        if (mode == 0)      m = ((const int*)maskv)[c] != 0;
        else if (mode == 1) m = ((const unsigned char*)maskv)[c] != 0;
        else                m = ((const float*)maskv)[c] != 0.0f;

        const float2* myp = (const float2*)(sp + tid * 30);

        if (!m) {
            float c0 = myp[2].x;   // float idx 4
            float c1 = myp[4].y;   // float idx 9
            s_noobj = c0 * c0 + c1 * c1;
        } else {
            float pv[30];
#pragma unroll
            for (int j = 0; j < 15; j++) {
                float2 v = myp[j];
                pv[2 * j]     = v.x;
                pv[2 * j + 1] = v.y;
            }

            // ---- class loss ----
            {
                const float4* myt = (const float4*)(st + tid * 20);
                float cls = 0.f;
#pragma unroll
                for (int j = 0; j < 5; j++) {
                    float4 t = myt[j];
                    float d0 = t.x - pv[10 + 4 * j + 0];
                    float d1 = t.y - pv[10 + 4 * j + 1];
                    float d2 = t.z - pv[10 + 4 * j + 2];
                    float d3 = t.w - pv[10 + 4 * j + 3];
                    cls += d0 * d0 + d1 * d1 + d2 * d2 + d3 * d3;
                }
                s_cls = cls;
            }

            // ---- IoU of the two pred boxes vs target ----
            float4 tb = __ldcs(((const float4*)tbox) + c);
            float t_cx = tb.x * S_GRID_INV;
            float t_cy = tb.y * S_GRID_INV;
            float t_x1 = t_cx - 0.5f * tb.z;
            float t_y1 = t_cy - 0.5f * tb.w;
            float t_x2 = t_cx + 0.5f * tb.z;
            float t_y2 = t_cy + 0.5f * tb.w;
            float area_t = (t_x2 - t_x1) * (t_y2 - t_y1);

            float iou[2];
#pragma unroll
            for (int b = 0; b < 2; b++) {
                float px = pv[5 * b + 0] * S_GRID_INV;
                float py = pv[5 * b + 1] * S_GRID_INV;
                float pw = pv[5 * b + 2];
                float ph = pv[5 * b + 3];
                float p_x1 = px - 0.5f * pw;
                float p_y1 = py - 0.5f * ph;
                float p_x2 = px + 0.5f * pw;
                float p_y2 = py + 0.5f * ph;
                float lt_x = fmaxf(t_x1, p_x1);
                float lt_y = fmaxf(t_y1, p_y1);
                float rb_x = fminf(t_x2, p_x2);
                float rb_y = fminf(t_y2, p_y2);
                float w = fmaxf(rb_x - lt_x, 0.0f);
                float h = fmaxf(rb_y - lt_y, 0.0f);
                float inter = w * h;
                float area_p = (p_x2 - p_x1) * (p_y2 - p_y1);
                iou[b] = inter / (area_t + area_p - inter);
            }

            // argmax (first max wins on tie)
            bool sel = iou[1] > iou[0];
            float best_iou = sel ? iou[1] : iou[0];
            float bb_x = sel ? pv[5] : pv[0];
            float bb_y = sel ? pv[6] : pv[1];
            float bb_w = sel ? pv[7] : pv[2];
            float bb_h = sel ? pv[8] : pv[3];
            float bb_c = sel ? pv[9] : pv[4];

            float dx = bb_x - tb.x;
            float dy = bb_y - tb.y;
            float sw = sqrtf(bb_w) - sqrtf(tb.z);
            float sh = sqrtf(bb_h) - sqrtf(tb.w);
            s_reg = dx * dx + dy * dy + sw * sw + sh * sh;

            float dc = best_iou - bb_c;
            s_cont = dc * dc;
        }
    }

    // ---- block reduction ----
#pragma unroll
    for (int off = 16; off; off >>= 1) {
        s_cls   += __shfl_down_sync(0xFFFFFFFFu, s_cls,   off);
        s_noobj += __shfl_down_sync(0xFFFFFFFFu, s_noobj, off);
        s_reg   += __shfl_down_sync(0xFFFFFFFFu, s_reg,   off);
        s_cont  += __shfl_down_sync(0xFFFFFFFFu, s_cont,  off);
    }

    __shared__ float sm[4][8];
    int wid = tid >> 5;
    int lid = tid & 31;
    if (lid == 0) {
        sm[0][wid] = s_cls;
        sm[1][wid] = s_noobj;
        sm[2][wid] = s_reg;
        sm[3][wid] = s_cont;
    }
    __syncthreads();

    if (tid == 0) {
        float a0 = 0.f, a1 = 0.f, a2 = 0.f, a3 = 0.f;
#pragma unroll
        for (int w = 0; w < 8; w++) {
            a0 += sm[0][w];
            a1 += sm[1][w];
            a2 += sm[2][w];
            a3 += sm[3][w];
        }
        atomicAdd(&g_acc[0], (double)a0);
        atomicAdd(&g_acc[1], (double)a1);
        atomicAdd(&g_acc[2], (double)a2);
        atomicAdd(&g_acc[3], (double)a3);

        __threadfence();
        unsigned old = atomicAdd(&g_counter, 1u);
        s_last = (old == gridDim.x - 1);
    }
    __syncthreads();

    // ---- last block: finalize + reset state for next graph replay ----
    if (s_last && tid == 0) {
        // atomicAdd(...,0.0) gives an ordered read of the final values
        double cls   = atomicAdd(&g_acc[0], 0.0);
        double noobj = (double)L_NOOBJ * atomicAdd(&g_acc[1], 0.0);
        double reg   = (double)L_COORD * atomicAdd(&g_acc[2], 0.0);
        double cont  = atomicAdd(&g_acc[3], 0.0);
        double total = (cls + noobj + reg + cont) / (double)n_batch;
        out[0] = (float)total;
        out[1] = (float)reg;
        out[2] = (float)cont;
        out[3] = (float)noobj;
        out[4] = (float)cls;
        // reset persistent state
        g_acc[0] = 0.0; g_acc[1] = 0.0; g_acc[2] = 0.0; g_acc[3] = 0.0;
        __threadfence();
        g_counter = 0u;
    }
}

extern "C" void kernel_launch(void* const* d_in, const int* in_sizes, int n_in,
                              void* d_out, int out_size) {
    // Identify inputs by element count: pred = 30n, tcls = 20n, tbox = 4n, mask = n
    const void* ptrs[4] = {d_in[0], d_in[1], d_in[2], d_in[3]};
    long long sz[4] = {in_sizes[0], in_sizes[1], in_sizes[2], in_sizes[3]};

    int im = 0;
    for (int i = 1; i < 4; i++) if (sz[i] < sz[im]) im = i;
    long long n = sz[im];

    const float* pred = nullptr;
    const float* tbox = nullptr;
    const float* tcls = nullptr;
    const void*  hmask = ptrs[im];
    for (int i = 0; i < 4; i++) {
        if (i == im) continue;
        if (sz[i] == 30 * n) pred = (const float*)ptrs[i];
        else if (sz[i] == 20 * n) tcls = (const float*)ptrs[i];
        else if (sz[i] == 4 * n) tbox = (const float*)ptrs[i];
    }

    int ncell = (int)n;                 // 802816
    int n_batch = ncell / (14 * 14);    // 4096

    int blocks = (ncell + TPB - 1) / TPB;  // 3136
    yolo_fused_kernel<<<blocks, TPB>>>(pred, tbox, tcls, hmask,
                                       ncell, n_batch, (float*)d_out);
}